// round 7
// baseline (speedup 1.0000x reference)
#include <cuda_runtime.h>
#include <cuda_fp16.h>
#include <cstdint>

#define Tn 17
#define Bn 4096
#define Cn 512
#define Dn 512
#define Kn 1024
#define TILE_M 128
#define TILE_N 256
#define NSTAGE 16
#define PIPE 4

// -------------------- scratch ------------------------------------------------
__device__ __align__(256) __half g_A[(size_t)Tn * Bn * Kn];  // ~143 MB
__device__ __align__(256) __half g_W[(size_t)Tn * Dn * Kn];  // ~18 MB
__device__ float g_bias[Tn * Dn];

// -------------------- helpers ------------------------------------------------
__device__ __forceinline__ uint32_t smem_u32(const void* p) {
    uint32_t a;
    asm("{ .reg .u64 t; cvta.to.shared.u64 t, %1; cvt.u32.u64 %0, t; }"
        : "=r"(a) : "l"(p));
    return a;
}

#define SWZ(o) ((o) ^ (((o) >> 3) & 0x70))

#define CP16(smem_addr, gptr) \
    asm volatile("cp.async.cg.shared.global [%0], [%1], 16;" \
                 :: "r"((uint32_t)(smem_addr)), "l"(gptr) : "memory")
#define CP_COMMIT()  asm volatile("cp.async.commit_group;" ::: "memory")
#define CP_WAIT_2()  asm volatile("cp.async.wait_group 2;" ::: "memory")

__device__ __forceinline__ void ldsm4(uint32_t* r, uint32_t addr) {
    asm volatile("ldmatrix.sync.aligned.m8n8.x4.shared.b16 {%0,%1,%2,%3}, [%4];"
                 : "=r"(r[0]), "=r"(r[1]), "=r"(r[2]), "=r"(r[3]) : "r"(addr));
}

// fp16-accumulate MMA: d,c in fp16x2 (2 regs)
__device__ __forceinline__ void mma16816h(uint32_t& c0, uint32_t& c1, const uint32_t* a,
                                          uint32_t b0, uint32_t b1) {
    asm volatile(
        "mma.sync.aligned.m16n8k16.row.col.f16.f16.f16.f16 "
        "{%0,%1}, {%2,%3,%4,%5}, {%6,%7}, {%0,%1};"
        : "+r"(c0), "+r"(c1)
        : "r"(a[0]), "r"(a[1]), "r"(a[2]), "r"(a[3]), "r"(b0), "r"(b1));
}

__device__ __forceinline__ void promote(float* acc, uint32_t c0, uint32_t c1) {
    const __half2 h0 = *reinterpret_cast<__half2*>(&c0);
    const __half2 h1 = *reinterpret_cast<__half2*>(&c1);
    const float2 f0 = __half22float2(h0);
    const float2 f1 = __half22float2(h1);
    acc[0] += f0.x; acc[1] += f0.y; acc[2] += f1.x; acc[3] += f1.y;
}

#define STAGE_BYTES 49152u            // A 16K + B 32K
#define SMEM_TOTAL  (PIPE * STAGE_BYTES)

// -------------------- prep: seasonal/trend -> fp16 ---------------------------
__device__ __forceinline__ void write_h(__half* ph, float4 v) {
    float a[4] = {v.x, v.y, v.z, v.w};
    uint2 uh;
    unsigned short h[4];
#pragma unroll
    for (int i = 0; i < 4; ++i) h[i] = __half_as_ushort(__float2half_rn(a[i]));
    uh.x = (uint32_t)h[0] | ((uint32_t)h[1] << 16);
    uh.y = (uint32_t)h[2] | ((uint32_t)h[3] << 16);
    *reinterpret_cast<uint2*>(ph) = uh;
}

__global__ void prep_kernel(const float* __restrict__ x) {
    const int b  = blockIdx.x;
    const int c4 = threadIdx.x;
    const float4* xb = reinterpret_cast<const float4*>(x) + (size_t)b * (Tn * Cn / 4);

    float4 v[Tn];
    float sx = 0.f, sy = 0.f, sz = 0.f, sw = 0.f;
#pragma unroll
    for (int t = 0; t < Tn; ++t) {
        v[t] = xb[t * (Cn / 4) + c4];
        sx += v[t].x; sy += v[t].y; sz += v[t].z; sw += v[t].w;
    }
    const float4 x0 = v[0];
    const float4 xl = v[Tn - 1];
    const float inv = 1.0f / 37.0f;

#pragma unroll
    for (int t = 0; t < Tn; ++t) {
        const float a = (float)(18 - t);
        const float c = (float)(t + 2);
        float4 tr, se;
        tr.x = (sx + a * x0.x + c * xl.x) * inv;
        tr.y = (sy + a * x0.y + c * xl.y) * inv;
        tr.z = (sz + a * x0.z + c * xl.z) * inv;
        tr.w = (sw + a * x0.w + c * xl.w) * inv;
        se.x = v[t].x - tr.x; se.y = v[t].y - tr.y;
        se.z = v[t].z - tr.z; se.w = v[t].w - tr.w;
        const size_t row = ((size_t)t * Bn + b) * Kn;
        write_h(g_A + row + c4 * 4,       se);
        write_h(g_A + row + 512 + c4 * 4, tr);
    }
}

__global__ void wprep_kernel(const float* __restrict__ Ws, const float* __restrict__ Wt,
                             const float* __restrict__ bs, const float* __restrict__ bt) {
    const size_t gid = (size_t)blockIdx.x * blockDim.x + threadIdx.x;
    const size_t total = (size_t)Tn * Dn * (Cn / 4);
    if (gid < total) {
        const size_t row = gid >> 7;
        const int    c4  = (int)(gid & 127);
        float4 s = reinterpret_cast<const float4*>(Ws)[row * 128 + c4];
        float4 t = reinterpret_cast<const float4*>(Wt)[row * 128 + c4];
        const size_t wrow = row * Kn;
        write_h(g_W + wrow + c4 * 4,       s);
        write_h(g_W + wrow + 512 + c4 * 4, t);
    }
    if (gid < (size_t)Tn * Dn) g_bias[gid] = bs[gid] + bt[gid];
}

// -------------------- mma.sync grouped GEMM (fp16 acc + fp32 promote) -------
__device__ __forceinline__ void load_stage(int s, int buf, int tid,
                                           size_t rowA0, size_t rowB0, uint32_t sb) {
    const size_t colByte = (size_t)s * 128;
    const uint32_t st = sb + (uint32_t)buf * STAGE_BYTES;
    const char* gA = (const char*)g_A;
    const char* gW = (const char*)g_W;
#pragma unroll
    for (int i = 0; i < 2; ++i) {
        const int idx = tid + i * 512;
        const int r = idx >> 3;
        const int cb = (idx & 7) * 16;
        const uint32_t sw = SWZ((uint32_t)(r * 128 + cb));
        CP16(st + sw, gA + (rowA0 + r) * (Kn * 2) + colByte + cb);
    }
#pragma unroll
    for (int i = 0; i < 4; ++i) {
        const int idx = tid + i * 512;
        const int r = idx >> 3;
        const int cb = (idx & 7) * 16;
        const uint32_t sw = SWZ((uint32_t)(r * 128 + cb));
        CP16(st + 16384u + sw, gW + (rowB0 + r) * (Kn * 2) + colByte + cb);
    }
}

__global__ __launch_bounds__(512, 1) void gemm_kernel(float* __restrict__ out) {
    extern __shared__ char smem[];
    const uint32_t sb = smem_u32(smem);
    const int tid = threadIdx.x, wid = tid >> 5, lane = tid & 31;
    const int bn = blockIdx.x, bm = blockIdx.y, t = blockIdx.z;

    const int wm = wid & 3;
    const int wn = wid >> 2;
    const int mbase = wm * 32;
    const int nbase = wn * 64;

    const int tid8 = lane >> 3;
    const int r8   = lane & 7;
    const int rowOff = ((tid8 & 1) << 3) + r8;
    const int colOff = (tid8 >> 1) << 4;

    // hoisted swizzle: SWZ(row*128 + k) = row*128 + (k ^ xorpat) for k < 128
    uint32_t aRow[2], aXor[2], bRow[4], bXor[4];
#pragma unroll
    for (int mf = 0; mf < 2; ++mf) {
        aRow[mf] = (uint32_t)(mbase + mf * 16 + rowOff) * 128u;
        aXor[mf] = (aRow[mf] >> 3) & 0x70u;
    }
#pragma unroll
    for (int g = 0; g < 4; ++g) {
        const uint32_t rb = (uint32_t)(nbase + g * 16 + rowOff) * 128u;
        bRow[g] = rb + 16384u;
        bXor[g] = (rb >> 3) & 0x70u;
    }

    const size_t rowA0 = (size_t)t * Bn + (size_t)bm * TILE_M;
    const size_t rowB0 = (size_t)t * Dn + (size_t)bn * TILE_N;

    float acc[2][8][4];
#pragma unroll
    for (int i = 0; i < 2; ++i)
#pragma unroll
        for (int j = 0; j < 8; ++j)
#pragma unroll
            for (int q = 0; q < 4; ++q) acc[i][j][q] = 0.f;

    load_stage(0, 0, tid, rowA0, rowB0, sb); CP_COMMIT();
    load_stage(1, 1, tid, rowA0, rowB0, sb); CP_COMMIT();
    load_stage(2, 2, tid, rowA0, rowB0, sb); CP_COMMIT();

    for (int ks = 0; ks < NSTAGE; ++ks) {
        const int buf = ks % PIPE;
        CP_WAIT_2();
        __syncthreads();
        if (ks + 3 < NSTAGE) load_stage(ks + 3, (ks + 3) % PIPE, tid, rowA0, rowB0, sb);
        CP_COMMIT();

        const uint32_t st = sb + (uint32_t)buf * STAGE_BYTES;

#pragma unroll
        for (int kkp = 0; kkp < 2; ++kkp) {  // k32 windows: kk pairs (0,1),(2,3)
            const uint32_t kc0 = (uint32_t)(kkp * 64 + colOff);       // kk even
            const uint32_t kc1 = kc0 + 32u;                           // kk odd

            uint32_t a0[2][4], a1[2][4];
#pragma unroll
            for (int mf = 0; mf < 2; ++mf) {
                ldsm4(a0[mf], st + aRow[mf] + (kc0 ^ aXor[mf]));
                ldsm4(a1[mf], st + aRow[mf] + (kc1 ^ aXor[mf]));
            }
#pragma unroll
            for (int g = 0; g < 4; ++g) {
                uint32_t b0[4], b1[4];
                ldsm4(b0, st + bRow[g] + (kc0 ^ bXor[g]));
                ldsm4(b1, st + bRow[g] + (kc1 ^ bXor[g]));
#pragma unroll
                for (int mf = 0; mf < 2; ++mf) {
#pragma unroll
                    for (int h = 0; h < 2; ++h) {
                        uint32_t c0 = 0u, c1 = 0u;
                        mma16816h(c0, c1, a0[mf], b0[h], b0[h + 2]);
                        mma16816h(c0, c1, a1[mf], b1[h], b1[h + 2]);
                        promote(acc[mf][g * 2 + h], c0, c1);
                    }
                }
            }
        }
        __syncthreads();
    }

    // -------------------- epilogue: bias + store --------------------
    const int qrow = lane >> 2;
    const int qcol = (lane & 3) * 2;
#pragma unroll
    for (int mf = 0; mf < 2; ++mf) {
        const size_t row0 = (size_t)bm * TILE_M + mbase + mf * 16 + qrow;
#pragma unroll
        for (int nf = 0; nf < 8; ++nf) {
            const int col = bn * TILE_N + nbase + nf * 8 + qcol;
            const float2 bv = *reinterpret_cast<const float2*>(g_bias + t * Dn + col);
            float2 o0, o1;
            o0.x = acc[mf][nf][0] + bv.x;
            o0.y = acc[mf][nf][1] + bv.y;
            o1.x = acc[mf][nf][2] + bv.x;
            o1.y = acc[mf][nf][3] + bv.y;
            *reinterpret_cast<float2*>(out + row0 * (Tn * Dn) + (size_t)t * Dn + col) = o0;
            *reinterpret_cast<float2*>(out + (row0 + 8) * (Tn * Dn) + (size_t)t * Dn + col) = o1;
        }
    }
}

// ---------------------------------------------------------------------------
extern "C" void kernel_launch(void* const* d_in, const int* in_sizes, int n_in,
                              void* d_out, int out_size) {
    const float* x  = (const float*)d_in[0];
    const float* Ws = (const float*)d_in[1];
    const float* bs = (const float*)d_in[2];
    const float* Wt = (const float*)d_in[3];
    const float* bt = (const float*)d_in[4];
    float* out = (float*)d_out;

    cudaFuncSetAttribute(gemm_kernel, cudaFuncAttributeMaxDynamicSharedMemorySize, SMEM_TOTAL);

    prep_kernel<<<Bn, 128>>>(x);

    const size_t wtotal = (size_t)Tn * Dn * (Cn / 4);
    wprep_kernel<<<(unsigned)((wtotal + 255) / 256), 256>>>(Ws, Wt, bs, bt);

    dim3 grid(Dn / TILE_N, Bn / TILE_M, Tn);
    gemm_kernel<<<grid, 512, SMEM_TOTAL>>>(out);
}

// round 8
// speedup vs baseline: 1.1866x; 1.1866x over previous
#include <cuda_runtime.h>
#include <cuda_fp16.h>
#include <cstdint>

#define Tn 17
#define Bn 4096
#define Cn 512
#define Dn 512
#define Kn 1024
#define TILE_M 128
#define TILE_N 256
#define NSTAGE 16
#define PIPE 3

#define ROW_PITCH 144u                 // 128B payload + 16B skew (bank-conflict-free ldsm)
#define A_BYTES   (128u * ROW_PITCH)   // 18432
#define B_OFF     A_BYTES
#define STAGE_BYTES (384u * ROW_PITCH) // 55296
#define MBAR_OFF  (PIPE * STAGE_BYTES) // 165888
#define SMEM_TOTAL (MBAR_OFF + 64u)
#define TX_BYTES  49152u               // 384 rows * 128B actual payload

// -------------------- scratch ------------------------------------------------
__device__ __align__(256) __half g_A[(size_t)Tn * Bn * Kn];  // ~143 MB
__device__ __align__(256) __half g_W[(size_t)Tn * Dn * Kn];  // ~18 MB
__device__ float g_bias[Tn * Dn];

// -------------------- helpers ------------------------------------------------
__device__ __forceinline__ uint32_t smem_u32(const void* p) {
    uint32_t a;
    asm("{ .reg .u64 t; cvta.to.shared.u64 t, %1; cvt.u32.u64 %0, t; }"
        : "=r"(a) : "l"(p));
    return a;
}

#define MBARRIER_INIT(mbar, cnt) \
    asm volatile("mbarrier.init.shared.b64 [%0], %1;" \
                 :: "r"((uint32_t)(mbar)), "r"((uint32_t)(cnt)) : "memory")

#define MBARRIER_EXPECT_TX(mbar, tx) \
    asm volatile("mbarrier.arrive.expect_tx.shared.b64 _, [%0], %1;" \
                 :: "r"((uint32_t)(mbar)), "r"((uint32_t)(tx)) : "memory")

#define MBARRIER_WAIT_PARITY(mbar, parity) do {                                   \
    uint32_t _m = (uint32_t)(mbar); uint32_t _p = (uint32_t)(parity);             \
    asm volatile(                                                                  \
        "{\n\t.reg .pred P1;\n\t"                                                  \
        "WAIT_LOOP_%=:\n\t"                                                        \
        "mbarrier.try_wait.parity.acquire.cta.shared::cta.b64 P1, [%0], %1, 0x989680;\n\t" \
        "@P1 bra.uni WAIT_DONE_%=;\n\t"                                            \
        "bra.uni WAIT_LOOP_%=;\n\t"                                                \
        "WAIT_DONE_%=:\n\t}"                                                       \
        :: "r"(_m), "r"(_p) : "memory");                                           \
} while (0)

#define BULK_CP(dst_smem, src_gmem, nbytes, mbar) \
    asm volatile("cp.async.bulk.shared::cluster.global.mbarrier::complete_tx::bytes " \
                 "[%0], [%1], %2, [%3];" \
                 :: "r"((uint32_t)(dst_smem)), "l"(src_gmem), \
                    "r"((uint32_t)(nbytes)), "r"((uint32_t)(mbar)) : "memory")

__device__ __forceinline__ void ldsm4(uint32_t* r, uint32_t addr) {
    asm volatile("ldmatrix.sync.aligned.m8n8.x4.shared.b16 {%0,%1,%2,%3}, [%4];"
                 : "=r"(r[0]), "=r"(r[1]), "=r"(r[2]), "=r"(r[3]) : "r"(addr));
}

__device__ __forceinline__ void mma16816(float* c, const uint32_t* a,
                                         uint32_t b0, uint32_t b1) {
    asm volatile(
        "mma.sync.aligned.m16n8k16.row.col.f32.f16.f16.f32 "
        "{%0,%1,%2,%3}, {%4,%5,%6,%7}, {%8,%9}, {%0,%1,%2,%3};"
        : "+f"(c[0]), "+f"(c[1]), "+f"(c[2]), "+f"(c[3])
        : "r"(a[0]), "r"(a[1]), "r"(a[2]), "r"(a[3]), "r"(b0), "r"(b1));
}

// -------------------- prep: seasonal/trend -> fp16 ---------------------------
__device__ __forceinline__ void write_h(__half* ph, float4 v) {
    float a[4] = {v.x, v.y, v.z, v.w};
    uint2 uh;
    unsigned short h[4];
#pragma unroll
    for (int i = 0; i < 4; ++i) h[i] = __half_as_ushort(__float2half_rn(a[i]));
    uh.x = (uint32_t)h[0] | ((uint32_t)h[1] << 16);
    uh.y = (uint32_t)h[2] | ((uint32_t)h[3] << 16);
    *reinterpret_cast<uint2*>(ph) = uh;
}

__global__ void prep_kernel(const float* __restrict__ x) {
    const int b  = blockIdx.x;
    const int c4 = threadIdx.x;
    const float4* xb = reinterpret_cast<const float4*>(x) + (size_t)b * (Tn * Cn / 4);

    float4 v[Tn];
    float sx = 0.f, sy = 0.f, sz = 0.f, sw = 0.f;
#pragma unroll
    for (int t = 0; t < Tn; ++t) {
        v[t] = xb[t * (Cn / 4) + c4];
        sx += v[t].x; sy += v[t].y; sz += v[t].z; sw += v[t].w;
    }
    const float4 x0 = v[0];
    const float4 xl = v[Tn - 1];
    const float inv = 1.0f / 37.0f;

#pragma unroll
    for (int t = 0; t < Tn; ++t) {
        const float a = (float)(18 - t);
        const float c = (float)(t + 2);
        float4 tr, se;
        tr.x = (sx + a * x0.x + c * xl.x) * inv;
        tr.y = (sy + a * x0.y + c * xl.y) * inv;
        tr.z = (sz + a * x0.z + c * xl.z) * inv;
        tr.w = (sw + a * x0.w + c * xl.w) * inv;
        se.x = v[t].x - tr.x; se.y = v[t].y - tr.y;
        se.z = v[t].z - tr.z; se.w = v[t].w - tr.w;
        const size_t row = ((size_t)t * Bn + b) * Kn;
        write_h(g_A + row + c4 * 4,       se);
        write_h(g_A + row + 512 + c4 * 4, tr);
    }
}

__global__ void wprep_kernel(const float* __restrict__ Ws, const float* __restrict__ Wt,
                             const float* __restrict__ bs, const float* __restrict__ bt) {
    const size_t gid = (size_t)blockIdx.x * blockDim.x + threadIdx.x;
    const size_t total = (size_t)Tn * Dn * (Cn / 4);
    if (gid < total) {
        const size_t row = gid >> 7;
        const int    c4  = (int)(gid & 127);
        float4 s = reinterpret_cast<const float4*>(Ws)[row * 128 + c4];
        float4 t = reinterpret_cast<const float4*>(Wt)[row * 128 + c4];
        const size_t wrow = row * Kn;
        write_h(g_W + wrow + c4 * 4,       s);
        write_h(g_W + wrow + 512 + c4 * 4, t);
    }
    if (gid < (size_t)Tn * Dn) g_bias[gid] = bs[gid] + bt[gid];
}

// -------------------- bulk-copy grouped GEMM --------------------------------
// Stage fill: 384 rows (A:128, B:256), one 128B cp.async.bulk per row, tid<384.
__device__ __forceinline__ void load_stage_bulk(int ks, uint32_t st, uint32_t mbar,
                                                int tid, size_t rowA0, size_t rowB0) {
    if (tid < 384) {
        const uint32_t colByte = (uint32_t)ks * 128u;
        if (tid < 128) {
            const char* src = (const char*)g_A + (rowA0 + tid) * (Kn * 2) + colByte;
            BULK_CP(st + (uint32_t)tid * ROW_PITCH, src, 128u, mbar);
        } else {
            const int rb = tid - 128;
            const char* src = (const char*)g_W + (rowB0 + rb) * (Kn * 2) + colByte;
            BULK_CP(st + B_OFF + (uint32_t)rb * ROW_PITCH, src, 128u, mbar);
        }
    }
}

__global__ __launch_bounds__(512, 1) void gemm_kernel(float* __restrict__ out) {
    extern __shared__ __align__(256) char smem[];
    const uint32_t sb = smem_u32(smem);
    const int tid = threadIdx.x, wid = tid >> 5, lane = tid & 31;
    const int bn = blockIdx.x, bm = blockIdx.y, t = blockIdx.z;

    const int wm = wid & 3;
    const int wn = wid >> 2;
    const int mbase = wm * 32;
    const int nbase = wn * 64;

    const int tid8 = lane >> 3;
    const int r8   = lane & 7;
    const int rowOff = ((tid8 & 1) << 3) + r8;   // 0..15
    const int colOff = (tid8 >> 1) << 4;         // 0 or 16

    // linear 144B-pitch addressing (no swizzle needed)
    uint32_t aRow[2], bRow[4];
#pragma unroll
    for (int mf = 0; mf < 2; ++mf)
        aRow[mf] = (uint32_t)(mbase + mf * 16 + rowOff) * ROW_PITCH;
#pragma unroll
    for (int g = 0; g < 4; ++g)
        bRow[g] = B_OFF + (uint32_t)(nbase + g * 16 + rowOff) * ROW_PITCH;

    const size_t rowA0 = (size_t)t * Bn + (size_t)bm * TILE_M;
    const size_t rowB0 = (size_t)t * Dn + (size_t)bn * TILE_N;

    // mbarriers
    const uint32_t mb = sb + MBAR_OFF;
    if (tid == 0) {
#pragma unroll
        for (int i = 0; i < PIPE; ++i) MBARRIER_INIT(mb + i * 8, 1);
    }
    __syncthreads();

    float acc[2][8][4];
#pragma unroll
    for (int i = 0; i < 2; ++i)
#pragma unroll
        for (int j = 0; j < 8; ++j)
#pragma unroll
            for (int q = 0; q < 4; ++q) acc[i][j][q] = 0.f;

    // prologue: stages 0,1 -> bufs 0,1
    if (tid == 0) {
        MBARRIER_EXPECT_TX(mb + 0, TX_BYTES);
        MBARRIER_EXPECT_TX(mb + 8, TX_BYTES);
    }
    __syncthreads();
    load_stage_bulk(0, sb, mb + 0, tid, rowA0, rowB0);
    load_stage_bulk(1, sb + STAGE_BYTES, mb + 8, tid, rowA0, rowB0);

    int parity0 = 0, parity1 = 0, parity2 = 0;

    for (int ks = 0; ks < NSTAGE; ++ks) {
        const int bufC = ks % PIPE;
        const int ksL = ks + 2;
        const int bufL = ksL % PIPE;

        // post expect_tx for the upcoming load (thread0 already done consuming bufL)
        if (tid == 0 && ksL < NSTAGE)
            MBARRIER_EXPECT_TX(mb + bufL * 8, TX_BYTES);
        __syncthreads();   // all warps done consuming bufL (used at iter ks-1)
        if (ksL < NSTAGE)
            load_stage_bulk(ksL, sb + (uint32_t)bufL * STAGE_BYTES, mb + bufL * 8,
                            tid, rowA0, rowB0);

        // wait for compute buffer
        {
            const int p = (bufC == 0) ? parity0 : (bufC == 1) ? parity1 : parity2;
            MBARRIER_WAIT_PARITY(mb + bufC * 8, p);
            if (bufC == 0) parity0 ^= 1; else if (bufC == 1) parity1 ^= 1; else parity2 ^= 1;
        }

        const uint32_t st = sb + (uint32_t)bufC * STAGE_BYTES;

#pragma unroll
        for (int kk = 0; kk < 4; ++kk) {
            const uint32_t kcb = (uint32_t)(kk * 32 + colOff);
            uint32_t ah[2][4], bh[4][4];
#pragma unroll
            for (int mf = 0; mf < 2; ++mf)
                ldsm4(ah[mf], st + aRow[mf] + kcb);
#pragma unroll
            for (int g = 0; g < 4; ++g)
                ldsm4(bh[g], st + bRow[g] + kcb);
#pragma unroll
            for (int mf = 0; mf < 2; ++mf)
#pragma unroll
                for (int g = 0; g < 4; ++g) {
                    mma16816(acc[mf][g * 2 + 0], ah[mf], bh[g][0], bh[g][2]);
                    mma16816(acc[mf][g * 2 + 1], ah[mf], bh[g][1], bh[g][3]);
                }
        }
    }

    // -------------------- epilogue: bias + store --------------------
    const int qrow = lane >> 2;
    const int qcol = (lane & 3) * 2;
#pragma unroll
    for (int mf = 0; mf < 2; ++mf) {
        const size_t row0 = (size_t)bm * TILE_M + mbase + mf * 16 + qrow;
#pragma unroll
        for (int nf = 0; nf < 8; ++nf) {
            const int col = bn * TILE_N + nbase + nf * 8 + qcol;
            const float2 bv = *reinterpret_cast<const float2*>(g_bias + t * Dn + col);
            float2 o0, o1;
            o0.x = acc[mf][nf][0] + bv.x;
            o0.y = acc[mf][nf][1] + bv.y;
            o1.x = acc[mf][nf][2] + bv.x;
            o1.y = acc[mf][nf][3] + bv.y;
            *reinterpret_cast<float2*>(out + row0 * (Tn * Dn) + (size_t)t * Dn + col) = o0;
            *reinterpret_cast<float2*>(out + (row0 + 8) * (Tn * Dn) + (size_t)t * Dn + col) = o1;
        }
    }
}

// ---------------------------------------------------------------------------
extern "C" void kernel_launch(void* const* d_in, const int* in_sizes, int n_in,
                              void* d_out, int out_size) {
    const float* x  = (const float*)d_in[0];
    const float* Ws = (const float*)d_in[1];
    const float* bs = (const float*)d_in[2];
    const float* Wt = (const float*)d_in[3];
    const float* bt = (const float*)d_in[4];
    float* out = (float*)d_out;

    cudaFuncSetAttribute(gemm_kernel, cudaFuncAttributeMaxDynamicSharedMemorySize, SMEM_TOTAL);

    prep_kernel<<<Bn, 128>>>(x);

    const size_t wtotal = (size_t)Tn * Dn * (Cn / 4);
    wprep_kernel<<<(unsigned)((wtotal + 255) / 256), 256>>>(Ws, Wt, bs, bt);

    dim3 grid(Dn / TILE_N, Bn / TILE_M, Tn);
    gemm_kernel<<<grid, 512, SMEM_TOTAL>>>(out);
}

// round 9
// speedup vs baseline: 1.5039x; 1.2674x over previous
#include <cuda_runtime.h>
#include <cuda_fp16.h>
#include <cstdint>

#define Tn 17
#define Bn 4096
#define Cn 512
#define Dn 512
#define Kn 1024
#define TILE_M 256
#define TILE_N 128
#define NSTAGE 16
#define PIPE 4

// -------------------- scratch ------------------------------------------------
__device__ __align__(256) __half g_A[(size_t)Tn * Bn * Kn];  // ~143 MB
__device__ __align__(256) __half g_W[(size_t)Tn * Dn * Kn];  // ~18 MB
__device__ float g_bias[Tn * Dn];

// -------------------- helpers ------------------------------------------------
__device__ __forceinline__ uint32_t smem_u32(const void* p) {
    uint32_t a;
    asm("{ .reg .u64 t; cvta.to.shared.u64 t, %1; cvt.u32.u64 %0, t; }"
        : "=r"(a) : "l"(p));
    return a;
}

#define SWZ(o) ((o) ^ (((o) >> 3) & 0x70))

#define CP16(smem_addr, gptr) \
    asm volatile("cp.async.cg.shared.global [%0], [%1], 16;" \
                 :: "r"((uint32_t)(smem_addr)), "l"(gptr) : "memory")
#define CP_COMMIT()  asm volatile("cp.async.commit_group;" ::: "memory")
#define CP_WAIT_2()  asm volatile("cp.async.wait_group 2;" ::: "memory")

__device__ __forceinline__ void ldsm4(uint32_t* r, uint32_t addr) {
    asm volatile("ldmatrix.sync.aligned.m8n8.x4.shared.b16 {%0,%1,%2,%3}, [%4];"
                 : "=r"(r[0]), "=r"(r[1]), "=r"(r[2]), "=r"(r[3]) : "r"(addr));
}

__device__ __forceinline__ void mma16816(float* c, const uint32_t* a,
                                         uint32_t b0, uint32_t b1) {
    asm volatile(
        "mma.sync.aligned.m16n8k16.row.col.f32.f16.f16.f32 "
        "{%0,%1,%2,%3}, {%4,%5,%6,%7}, {%8,%9}, {%0,%1,%2,%3};"
        : "+f"(c[0]), "+f"(c[1]), "+f"(c[2]), "+f"(c[3])
        : "r"(a[0]), "r"(a[1]), "r"(a[2]), "r"(a[3]), "r"(b0), "r"(b1));
}

// SMEM: PIPE x (A 32K | B 16K) = 4 x 48K = 192K
#define STAGE_BYTES 49152u
#define B_OFF 32768u
#define SMEM_TOTAL (PIPE * STAGE_BYTES)

// -------------------- prep: seasonal/trend -> fp16 ---------------------------
__device__ __forceinline__ void write_h(__half* ph, float4 v) {
    float a[4] = {v.x, v.y, v.z, v.w};
    uint2 uh;
    unsigned short h[4];
#pragma unroll
    for (int i = 0; i < 4; ++i) h[i] = __half_as_ushort(__float2half_rn(a[i]));
    uh.x = (uint32_t)h[0] | ((uint32_t)h[1] << 16);
    uh.y = (uint32_t)h[2] | ((uint32_t)h[3] << 16);
    *reinterpret_cast<uint2*>(ph) = uh;
}

__global__ void prep_kernel(const float* __restrict__ x) {
    const int b  = blockIdx.x;
    const int c4 = threadIdx.x;
    const float4* xb = reinterpret_cast<const float4*>(x) + (size_t)b * (Tn * Cn / 4);

    float4 v[Tn];
    float sx = 0.f, sy = 0.f, sz = 0.f, sw = 0.f;
#pragma unroll
    for (int t = 0; t < Tn; ++t) {
        v[t] = xb[t * (Cn / 4) + c4];
        sx += v[t].x; sy += v[t].y; sz += v[t].z; sw += v[t].w;
    }
    const float4 x0 = v[0];
    const float4 xl = v[Tn - 1];
    const float inv = 1.0f / 37.0f;

#pragma unroll
    for (int t = 0; t < Tn; ++t) {
        const float a = (float)(18 - t);
        const float c = (float)(t + 2);
        float4 tr, se;
        tr.x = (sx + a * x0.x + c * xl.x) * inv;
        tr.y = (sy + a * x0.y + c * xl.y) * inv;
        tr.z = (sz + a * x0.z + c * xl.z) * inv;
        tr.w = (sw + a * x0.w + c * xl.w) * inv;
        se.x = v[t].x - tr.x; se.y = v[t].y - tr.y;
        se.z = v[t].z - tr.z; se.w = v[t].w - tr.w;
        const size_t row = ((size_t)t * Bn + b) * Kn;
        write_h(g_A + row + c4 * 4,       se);
        write_h(g_A + row + 512 + c4 * 4, tr);
    }
}

__global__ void wprep_kernel(const float* __restrict__ Ws, const float* __restrict__ Wt,
                             const float* __restrict__ bs, const float* __restrict__ bt) {
    const size_t gid = (size_t)blockIdx.x * blockDim.x + threadIdx.x;
    const size_t total = (size_t)Tn * Dn * (Cn / 4);
    if (gid < total) {
        const size_t row = gid >> 7;
        const int    c4  = (int)(gid & 127);
        float4 s = reinterpret_cast<const float4*>(Ws)[row * 128 + c4];
        float4 t = reinterpret_cast<const float4*>(Wt)[row * 128 + c4];
        const size_t wrow = row * Kn;
        write_h(g_W + wrow + c4 * 4,       s);
        write_h(g_W + wrow + 512 + c4 * 4, t);
    }
    if (gid < (size_t)Tn * Dn) g_bias[gid] = bs[gid] + bt[gid];
}

// -------------------- mma.sync grouped GEMM (64x64 warp tiles) --------------
__device__ __forceinline__ void load_stage(int s, int buf, int tid,
                                           size_t rowA0, size_t rowB0, uint32_t sb) {
    const size_t colByte = (size_t)s * 128;
    const uint32_t st = sb + (uint32_t)buf * STAGE_BYTES;
    const char* gA = (const char*)g_A;
    const char* gW = (const char*)g_W;
#pragma unroll
    for (int i = 0; i < 8; ++i) {           // A: 256 rows x 8 lines = 2048 / 256 thr
        const int idx = tid + i * 256;
        const int r = idx >> 3;
        const int cb = (idx & 7) * 16;
        const uint32_t sw = SWZ((uint32_t)(r * 128 + cb));
        CP16(st + sw, gA + (rowA0 + r) * (Kn * 2) + colByte + cb);
    }
#pragma unroll
    for (int i = 0; i < 4; ++i) {           // B: 128 rows x 8 lines = 1024 / 256 thr
        const int idx = tid + i * 256;
        const int r = idx >> 3;
        const int cb = (idx & 7) * 16;
        const uint32_t sw = SWZ((uint32_t)(r * 128 + cb));
        CP16(st + B_OFF + sw, gW + (rowB0 + r) * (Kn * 2) + colByte + cb);
    }
}

__global__ __launch_bounds__(256, 1) void gemm_kernel(float* __restrict__ out) {
    extern __shared__ char smem[];
    const uint32_t sb = smem_u32(smem);
    const int tid = threadIdx.x, wid = tid >> 5, lane = tid & 31;
    const int bn = blockIdx.x, bm = blockIdx.y, t = blockIdx.z;

    const int wm = wid & 3;          // 4 warps in M (64 rows each)
    const int wn = wid >> 2;         // 2 warps in N (64 cols each)
    const int mbase = wm * 64;
    const int nbase = wn * 64;

    const int tid8 = lane >> 3;
    const int r8   = lane & 7;
    const int rowOff = ((tid8 & 1) << 3) + r8;   // 0..15
    const int colOff = (tid8 >> 1) << 4;         // 0 or 16

    // hoisted swizzle: SWZ(row*128 + k) = row*128 + (k ^ xorpat), k < 128
    uint32_t aRow[4], aXor[4], bRow[4], bXor[4];
#pragma unroll
    for (int mf = 0; mf < 4; ++mf) {
        aRow[mf] = (uint32_t)(mbase + mf * 16 + rowOff) * 128u;
        aXor[mf] = (aRow[mf] >> 3) & 0x70u;
    }
#pragma unroll
    for (int g = 0; g < 4; ++g) {
        const uint32_t rb = (uint32_t)(nbase + g * 16 + rowOff) * 128u;
        bRow[g] = rb + B_OFF;
        bXor[g] = (rb >> 3) & 0x70u;
    }

    const size_t rowA0 = (size_t)t * Bn + (size_t)bm * TILE_M;
    const size_t rowB0 = (size_t)t * Dn + (size_t)bn * TILE_N;

    float acc[4][8][4];
#pragma unroll
    for (int i = 0; i < 4; ++i)
#pragma unroll
        for (int j = 0; j < 8; ++j)
#pragma unroll
            for (int q = 0; q < 4; ++q) acc[i][j][q] = 0.f;

    load_stage(0, 0, tid, rowA0, rowB0, sb); CP_COMMIT();
    load_stage(1, 1, tid, rowA0, rowB0, sb); CP_COMMIT();
    load_stage(2, 2, tid, rowA0, rowB0, sb); CP_COMMIT();

    for (int ks = 0; ks < NSTAGE; ++ks) {
        const int buf = ks % PIPE;
        CP_WAIT_2();
        __syncthreads();
        if (ks + 3 < NSTAGE) load_stage(ks + 3, (ks + 3) % PIPE, tid, rowA0, rowB0, sb);
        CP_COMMIT();

        const uint32_t st = sb + (uint32_t)buf * STAGE_BYTES;

#pragma unroll
        for (int kk = 0; kk < 4; ++kk) {
            const uint32_t kcb = (uint32_t)(kk * 32 + colOff);
            uint32_t ah[4][4], bh[4][4];
#pragma unroll
            for (int mf = 0; mf < 4; ++mf)
                ldsm4(ah[mf], st + aRow[mf] + (kcb ^ aXor[mf]));
#pragma unroll
            for (int g = 0; g < 4; ++g)
                ldsm4(bh[g], st + bRow[g] + (kcb ^ bXor[g]));
#pragma unroll
            for (int mf = 0; mf < 4; ++mf)
#pragma unroll
                for (int g = 0; g < 4; ++g) {
                    mma16816(acc[mf][g * 2 + 0], ah[mf], bh[g][0], bh[g][2]);
                    mma16816(acc[mf][g * 2 + 1], ah[mf], bh[g][1], bh[g][3]);
                }
        }
    }

    // -------------------- epilogue: bias + store --------------------
    const int qrow = lane >> 2;
    const int qcol = (lane & 3) * 2;
#pragma unroll
    for (int mf = 0; mf < 4; ++mf) {
        const size_t row0 = (size_t)bm * TILE_M + mbase + mf * 16 + qrow;
#pragma unroll
        for (int nf = 0; nf < 8; ++nf) {
            const int col = bn * TILE_N + nbase + nf * 8 + qcol;
            const float2 bv = *reinterpret_cast<const float2*>(g_bias + t * Dn + col);
            float2 o0, o1;
            o0.x = acc[mf][nf][0] + bv.x;
            o0.y = acc[mf][nf][1] + bv.y;
            o1.x = acc[mf][nf][2] + bv.x;
            o1.y = acc[mf][nf][3] + bv.y;
            *reinterpret_cast<float2*>(out + row0 * (Tn * Dn) + (size_t)t * Dn + col) = o0;
            *reinterpret_cast<float2*>(out + (row0 + 8) * (Tn * Dn) + (size_t)t * Dn + col) = o1;
        }
    }
}

// ---------------------------------------------------------------------------
extern "C" void kernel_launch(void* const* d_in, const int* in_sizes, int n_in,
                              void* d_out, int out_size) {
    const float* x  = (const float*)d_in[0];
    const float* Ws = (const float*)d_in[1];
    const float* bs = (const float*)d_in[2];
    const float* Wt = (const float*)d_in[3];
    const float* bt = (const float*)d_in[4];
    float* out = (float*)d_out;

    cudaFuncSetAttribute(gemm_kernel, cudaFuncAttributeMaxDynamicSharedMemorySize, SMEM_TOTAL);

    prep_kernel<<<Bn, 128>>>(x);

    const size_t wtotal = (size_t)Tn * Dn * (Cn / 4);
    wprep_kernel<<<(unsigned)((wtotal + 255) / 256), 256>>>(Ws, Wt, bs, bt);

    dim3 grid(Dn / TILE_N, Bn / TILE_M, Tn);
    gemm_kernel<<<grid, 256, SMEM_TOTAL>>>(out);
}